// round 16
// baseline (speedup 1.0000x reference)
#include <cuda_runtime.h>
#include <cuda_fp16.h>

#define HD   160
#define PLN  25600          // W*D
#define VOL  4096000        // H*W*D
#define NVOX 8192000ULL     // 2*160^3
#define WSEG 80             // passDW w-outputs per block
#define NR   90             // rows processed per passDW block (WSEG + 10)
#define PRE  4              // smem prefetch depth (rows)
#define RING 6              // smem row-ring slots
#define SEG  80             // passH slide segment
#define NBBC 640            // passH grid blocks: 2*160*2

typedef unsigned long long ull;

// Normalized 1D Gaussian, KS=11, sigma=1.5
__device__ constexpr float GW[11] = {
    0.00102838f, 0.00759876f, 0.03600077f, 0.10936070f, 0.21300553f,
    0.26601172f,
    0.21300553f, 0.10936070f, 0.03600077f, 0.00759876f, 0.00102838f
};

constexpr float C1f  = 1.0e-4f;
constexpr float C2f  = 9.0e-4f;
constexpr float EPSf = 1.0e-12f;

// Interleaved fp16 scratch: one 16-byte record per voxel (f0..f4 + pad).
__device__ uint4 gI[NVOX];
__device__ double g_acc;
__device__ unsigned int g_ticket;

__device__ __forceinline__ int refl(int i) {
    return (i < 0) ? -i : ((i > HD - 1) ? (2 * (HD - 1) - i) : i);
}

// ---- packed f32x2 helpers (for passH) --------------------------------------
__device__ __forceinline__ ull pack2(float x, float y) {
    ull r; asm("mov.b64 %0, {%1, %2};" : "=l"(r) : "f"(x), "f"(y)); return r;
}
__device__ __forceinline__ void unpack2(float& x, float& y, ull v) {
    asm("mov.b64 {%0, %1}, %2;" : "=f"(x), "=f"(y) : "l"(v));
}
__device__ __forceinline__ ull fma2(ull a, ull b, ull c) {
    ull d; asm("fma.rn.f32x2 %0, %1, %2, %3;" : "=l"(d) : "l"(a), "l"(b), "l"(c));
    return d;
}

// ---------------------------------------------------------------------------
// passDW: fused D-blur (+5 field products) and W-blur (exact R12 body);
// ONLY change: block barrier every 2 iterations (j even). Safe with RING=6,
// PRE=4: between barriers iters {j,j+1} read slots {j,j+1}%6 and write
// {j+4,j+5}%6 (disjoint); every write->read (distance 4) crosses a barrier.
// Block = (w-half 80, h, b), 160 threads (t = d).
// ---------------------------------------------------------------------------
__global__ void __launch_bounds__(HD) passDW(const float* __restrict__ src,
                                             const float* __restrict__ ref) {
    __shared__ float S[RING][172];
    __shared__ float R[RING][172];

    const int t  = threadIdx.x;
    const int b  = blockIdx.z;
    const int h  = blockIdx.y;
    const int w0 = blockIdx.x * WSEG;

    const size_t bh = ((size_t)(b * HD + h)) * PLN;

    const bool loT = (t < 6);
    const bool hiT = (t >= 154);
    const int  hpos = loT ? t : (t + 12);            // halo smem position
    const int  hgl  = loT ? (6 - t) : (312 - t);     // halo global d

    // Prologue: rows 0..PRE-1 straight into smem.
    for (int m = 0; m < PRE; ++m) {
        const size_t base = bh + (size_t)refl(w0 - 5 + m) * HD;
        S[m][6 + t] = __ldg(src + base + t);
        R[m][6 + t] = __ldg(ref + base + t);
        if (loT || hiT) {
            S[m][hpos] = __ldg(src + base + hgl);
            R[m][hpos] = __ldg(ref + base + hgl);
        }
    }
    // Prefetch row PRE into registers.
    float sM, rM, sH = 0.f, rH = 0.f;
    {
        const size_t base = bh + (size_t)refl(w0 - 5 + PRE) * HD;
        sM = __ldg(src + base + t);
        rM = __ldg(ref + base + t);
        if (loT || hiT) { sH = __ldg(src + base + hgl); rH = __ldg(ref + base + hgl); }
    }

    // Register ring of D-blurred fields.
    float q0[11], q1[11], q2[11], q3[11], q4[11];

    int scur = 0;        // j % RING
    int spre = PRE;      // (j+PRE) % RING

    #pragma unroll 1
    for (int c = 0; c < 9; ++c) {
        const int cpar = c & 1;
        #pragma unroll
        for (int u = 0; u < 11; ++u) {
            const int j = c * 11 + u;
            if (j >= NR) break;
            if ((u & 1) == cpar) __syncthreads();   // barrier when j is even

            // Retire prefetched row j+PRE into smem, then prefetch j+PRE+1.
            if (j + PRE < NR) {
                S[spre][6 + t] = sM;
                R[spre][6 + t] = rM;
                if (loT || hiT) { S[spre][hpos] = sH; R[spre][hpos] = rH; }
                if (j + PRE + 1 < NR) {
                    const size_t base = bh + (size_t)refl(w0 - 5 + j + PRE + 1) * HD;
                    sM = __ldg(src + base + t);
                    rM = __ldg(ref + base + t);
                    if (loT || hiT) { sH = __ldg(src + base + hgl); rH = __ldg(ref + base + hgl); }
                }
            }

            // D-blur row j (slot scur) -> ring slot u (== j % 11).
            float a0 = 0.f, a1 = 0.f, a2 = 0.f, a3 = 0.f, a4 = 0.f;
            #pragma unroll
            for (int k = 0; k < 11; ++k) {
                const float s = S[scur][t + 1 + k];
                const float v = R[scur][t + 1 + k];
                const float ss = s * s, vv = v * v, sv = s * v;
                a0 = fmaf(GW[k], s,  a0);
                a1 = fmaf(GW[k], v,  a1);
                a2 = fmaf(GW[k], ss, a2);
                a3 = fmaf(GW[k], vv, a3);
                a4 = fmaf(GW[k], sv, a4);
            }
            q0[u] = a0; q1[u] = a1; q2[u] = a2; q3[u] = a3; q4[u] = a4;

            if (++scur == RING) scur = 0;
            if (++spre == RING) spre = 0;

            // W-blur output w = w0 + j - 10 from ring rows j-10..j.
            if (j >= 10) {
                float m0 = 0.f, m1 = 0.f, m2 = 0.f, m3 = 0.f, m4 = 0.f;
                #pragma unroll
                for (int k = 0; k < 11; ++k) {
                    const int s2 = (u + 1 + k) % 11;
                    m0 = fmaf(GW[k], q0[s2], m0);
                    m1 = fmaf(GW[k], q1[s2], m1);
                    m2 = fmaf(GW[k], q2[s2], m2);
                    m3 = fmaf(GW[k], q3[s2], m3);
                    m4 = fmaf(GW[k], q4[s2], m4);
                }
                uint4 rec;
                *reinterpret_cast<__half2*>(&rec.x) = __floats2half2_rn(m0, m1);
                *reinterpret_cast<__half2*>(&rec.y) = __floats2half2_rn(m2, m3);
                *reinterpret_cast<__half2*>(&rec.z) = __floats2half2_rn(m4, 0.f);
                rec.w = 0u;
                gI[bh + (size_t)(w0 + j - 10) * HD + t] = rec;
            }
        }
    }
}

// ---------------------------------------------------------------------------
// passH: H-blur + SSIM + reduce. 14-SLOT ring, prefetch distance 2:
// iter j loads plane h0+j+7 into slot (u+12)%14, first read at iter j+2
// (k=10). Reads at iter j are slots (u+k)%14, k=0..10. f32x2 tap math.
// Block (h-seg 80, w, b), 160 threads.
// ---------------------------------------------------------------------------
__global__ void __launch_bounds__(HD) passH(float* __restrict__ out) {
    const int d  = threadIdx.x;
    const int b  = blockIdx.z;
    const int w  = blockIdx.y;
    const int h0 = blockIdx.x * SEG;

    const size_t bw = (size_t)b * VOL + (size_t)w * HD + d;

    ull W2[11];
    #pragma unroll
    for (int k = 0; k < 11; ++k) W2[k] = pack2(GW[k], GW[k]);

    ull  win01[14], win23[14];
    float win4[14];

    // Warm-up: planes h0-5 .. h0+6 into slots 0..11.
    #pragma unroll
    for (int m = 0; m < 12; ++m) {
        const uint4 v = __ldg(gI + bw + (size_t)refl(h0 - 5 + m) * PLN);
        const float2 f01 = __half22float2(*reinterpret_cast<const __half2*>(&v.x));
        const float2 f23 = __half22float2(*reinterpret_cast<const __half2*>(&v.y));
        const float2 f4  = __half22float2(*reinterpret_cast<const __half2*>(&v.z));
        win01[m] = pack2(f01.x, f01.y);
        win23[m] = pack2(f23.x, f23.y);
        win4[m]  = f4.x;
    }

    float acc = 0.f;

    #pragma unroll 1
    for (int c = 0; c < (SEG + 13) / 14; ++c) {
        const int jbase = c * 14;
        #pragma unroll
        for (int u = 0; u < 14; ++u) {
            const int j = jbase + u;
            if (j >= SEG) break;
            {   // load plane h0+j+7 into slot (u+12)%14 (first read iter j+2)
                const uint4 v = __ldg(gI + bw + (size_t)refl(h0 + j + 7) * PLN);
                const float2 f01 = __half22float2(*reinterpret_cast<const __half2*>(&v.x));
                const float2 f23 = __half22float2(*reinterpret_cast<const __half2*>(&v.y));
                const float2 f4  = __half22float2(*reinterpret_cast<const __half2*>(&v.z));
                const int sl = (u + 12) % 14;
                win01[sl] = pack2(f01.x, f01.y);
                win23[sl] = pack2(f23.x, f23.y);
                win4[sl]  = f4.x;
            }
            ull mu12 = 0ULL, mm = 0ULL;
            float m12 = 0.f;
            #pragma unroll
            for (int k = 0; k < 11; ++k) {
                const int sl = (u + k) % 14;
                mu12 = fma2(W2[k], win01[sl], mu12);   // (mu1, mu2)
                mm   = fma2(W2[k], win23[sl], mm);     // (m11, m22)
                m12  = fmaf(GW[k], win4[sl], m12);
            }
            float mu1, mu2, m11, m22;
            unpack2(mu1, mu2, mu12);
            unpack2(m11, m22, mm);

            const float a  = mu1 * mu1;
            const float bb = mu2 * mu2;
            const float cc = mu1 * mu2;
            const float s1 = m11 - a, s2 = m22 - bb, s12 = m12 - cc;
            const float num = (2.f * cc + C1f) * (2.f * s12 + C2f);
            const float den = (a + bb + C1f) * (s1 + s2 + C2f);
            acc += __fdividef(num, den + EPSf);
        }
    }

    // Reduce: 5 warps -> smem -> atomicAdd(double), ticket finalize.
    float v = acc;
    #pragma unroll
    for (int o = 16; o > 0; o >>= 1) v += __shfl_down_sync(0xffffffffu, v, o);
    __shared__ float ws[5];
    if ((threadIdx.x & 31) == 0) ws[threadIdx.x >> 5] = v;
    __syncthreads();
    if (threadIdx.x == 0) {
        const float s = ws[0] + ws[1] + ws[2] + ws[3] + ws[4];
        atomicAdd(&g_acc, (double)s);
        __threadfence();
        const unsigned done = atomicAdd(&g_ticket, 1u);
        if (done == NBBC - 1) {
            const double vv = atomicAdd(&g_acc, 0.0);
            out[0] = (float)(1.0 - vv / (double)NVOX);
            g_acc = 0.0;
            g_ticket = 0u;
            __threadfence();
        }
    }
}

extern "C" void kernel_launch(void* const* d_in, const int* in_sizes, int n_in,
                              void* d_out, int out_size) {
    const float* src = (const float*)d_in[0];
    const float* ref = (const float*)d_in[1];
    float* out = (float*)d_out;

    passDW<<<dim3(HD / WSEG, HD, 2), HD>>>(src, ref);
    passH<<<dim3(HD / SEG, HD, 2), HD>>>(out);
}

// round 17
// speedup vs baseline: 1.1559x; 1.1559x over previous
#include <cuda_runtime.h>
#include <cuda_fp16.h>

#define HD   160
#define PLN  25600          // W*D
#define VOL  4096000        // H*W*D
#define NVOX 8192000ULL     // 2*160^3
#define WSEG 80             // passDW w-outputs per block
#define NR   90             // rows processed per passDW block (WSEG + 10)
#define PRE  4              // smem prefetch depth (rows)
#define RING 6              // smem row-ring slots
#define SEG  80             // passH slide segment
#define NBBC 640            // passH grid blocks: 2*160*2

typedef unsigned long long ull;

// Normalized 1D Gaussian, KS=11, sigma=1.5
__device__ constexpr float GW[11] = {
    0.00102838f, 0.00759876f, 0.03600077f, 0.10936070f, 0.21300553f,
    0.26601172f,
    0.21300553f, 0.10936070f, 0.03600077f, 0.00759876f, 0.00102838f
};

constexpr float C1f  = 1.0e-4f;
constexpr float C2f  = 9.0e-4f;
constexpr float EPSf = 1.0e-12f;

// Interleaved fp16 scratch: one 16-byte record per voxel (f0..f4 + pad).
__device__ uint4 gI[NVOX];
__device__ double g_acc;
__device__ unsigned int g_ticket;

__device__ __forceinline__ int refl(int i) {
    return (i < 0) ? -i : ((i > HD - 1) ? (2 * (HD - 1) - i) : i);
}

// ---- packed f32x2 helpers (for passH) --------------------------------------
__device__ __forceinline__ ull pack2(float x, float y) {
    ull r; asm("mov.b64 %0, {%1, %2};" : "=l"(r) : "f"(x), "f"(y)); return r;
}
__device__ __forceinline__ void unpack2(float& x, float& y, ull v) {
    asm("mov.b64 {%0, %1}, %2;" : "=f"(x), "=f"(y) : "l"(v));
}
__device__ __forceinline__ ull fma2(ull a, ull b, ull c) {
    ull d; asm("fma.rn.f32x2 %0, %1, %2, %3;" : "=l"(d) : "l"(a), "l"(b), "l"(c));
    return d;
}

// ---------------------------------------------------------------------------
// passDW: fused D-blur (+5 field products) and W-blur — EXACT R12 body.
// Single change: __launch_bounds__(160, 5) to force >=5 resident blocks/SM
// (regs <= 81), raising the latency-hiding warp pool by 25%.
// Block = (w-half 80, h, b), 160 threads (t = d).
// ---------------------------------------------------------------------------
__global__ void __launch_bounds__(HD, 5) passDW(const float* __restrict__ src,
                                                const float* __restrict__ ref) {
    __shared__ float S[RING][172];
    __shared__ float R[RING][172];

    const int t  = threadIdx.x;
    const int b  = blockIdx.z;
    const int h  = blockIdx.y;
    const int w0 = blockIdx.x * WSEG;

    const size_t bh = ((size_t)(b * HD + h)) * PLN;

    const bool loT = (t < 6);
    const bool hiT = (t >= 154);
    const int  hpos = loT ? t : (t + 12);            // halo smem position
    const int  hgl  = loT ? (6 - t) : (312 - t);     // halo global d

    // Prologue: rows 0..PRE-1 straight into smem.
    for (int m = 0; m < PRE; ++m) {
        const size_t base = bh + (size_t)refl(w0 - 5 + m) * HD;
        S[m][6 + t] = __ldg(src + base + t);
        R[m][6 + t] = __ldg(ref + base + t);
        if (loT || hiT) {
            S[m][hpos] = __ldg(src + base + hgl);
            R[m][hpos] = __ldg(ref + base + hgl);
        }
    }
    // Prefetch row PRE into registers.
    float sM, rM, sH = 0.f, rH = 0.f;
    {
        const size_t base = bh + (size_t)refl(w0 - 5 + PRE) * HD;
        sM = __ldg(src + base + t);
        rM = __ldg(ref + base + t);
        if (loT || hiT) { sH = __ldg(src + base + hgl); rH = __ldg(ref + base + hgl); }
    }

    // Register ring of D-blurred fields.
    float q0[11], q1[11], q2[11], q3[11], q4[11];

    int scur = 0;        // j % RING
    int spre = PRE;      // (j+PRE) % RING

    #pragma unroll 1
    for (int c = 0; c < 9; ++c) {
        #pragma unroll
        for (int u = 0; u < 11; ++u) {
            const int j = c * 11 + u;
            if (j >= NR) break;
            __syncthreads();

            // Retire prefetched row j+PRE into smem, then prefetch j+PRE+1.
            if (j + PRE < NR) {
                S[spre][6 + t] = sM;
                R[spre][6 + t] = rM;
                if (loT || hiT) { S[spre][hpos] = sH; R[spre][hpos] = rH; }
                if (j + PRE + 1 < NR) {
                    const size_t base = bh + (size_t)refl(w0 - 5 + j + PRE + 1) * HD;
                    sM = __ldg(src + base + t);
                    rM = __ldg(ref + base + t);
                    if (loT || hiT) { sH = __ldg(src + base + hgl); rH = __ldg(ref + base + hgl); }
                }
            }

            // D-blur row j (slot scur) -> ring slot u (== j % 11).
            float a0 = 0.f, a1 = 0.f, a2 = 0.f, a3 = 0.f, a4 = 0.f;
            #pragma unroll
            for (int k = 0; k < 11; ++k) {
                const float s = S[scur][t + 1 + k];
                const float v = R[scur][t + 1 + k];
                const float ss = s * s, vv = v * v, sv = s * v;
                a0 = fmaf(GW[k], s,  a0);
                a1 = fmaf(GW[k], v,  a1);
                a2 = fmaf(GW[k], ss, a2);
                a3 = fmaf(GW[k], vv, a3);
                a4 = fmaf(GW[k], sv, a4);
            }
            q0[u] = a0; q1[u] = a1; q2[u] = a2; q3[u] = a3; q4[u] = a4;

            if (++scur == RING) scur = 0;
            if (++spre == RING) spre = 0;

            // W-blur output w = w0 + j - 10 from ring rows j-10..j.
            if (j >= 10) {
                float m0 = 0.f, m1 = 0.f, m2 = 0.f, m3 = 0.f, m4 = 0.f;
                #pragma unroll
                for (int k = 0; k < 11; ++k) {
                    const int s2 = (u + 1 + k) % 11;
                    m0 = fmaf(GW[k], q0[s2], m0);
                    m1 = fmaf(GW[k], q1[s2], m1);
                    m2 = fmaf(GW[k], q2[s2], m2);
                    m3 = fmaf(GW[k], q3[s2], m3);
                    m4 = fmaf(GW[k], q4[s2], m4);
                }
                uint4 rec;
                *reinterpret_cast<__half2*>(&rec.x) = __floats2half2_rn(m0, m1);
                *reinterpret_cast<__half2*>(&rec.y) = __floats2half2_rn(m2, m3);
                *reinterpret_cast<__half2*>(&rec.z) = __floats2half2_rn(m4, 0.f);
                rec.w = 0u;
                gI[bh + (size_t)(w0 + j - 10) * HD + t] = rec;
            }
        }
    }
}

// ---------------------------------------------------------------------------
// passH: H-blur + SSIM + reduce — EXACT R14 form (measured 48.1 us).
// 12-slot ring, LDG.128 interleaved record, f32x2 tap math.
// Block (h-seg 80, w, b), 160 threads.
// ---------------------------------------------------------------------------
__global__ void __launch_bounds__(HD) passH(float* __restrict__ out) {
    const int d  = threadIdx.x;
    const int b  = blockIdx.z;
    const int w  = blockIdx.y;
    const int h0 = blockIdx.x * SEG;

    const size_t bw = (size_t)b * VOL + (size_t)w * HD + d;

    ull W2[11];
    #pragma unroll
    for (int k = 0; k < 11; ++k) W2[k] = pack2(GW[k], GW[k]);

    ull  win01[12], win23[12];
    float win4[12];

    #pragma unroll
    for (int m = 0; m < 11; ++m) {
        const uint4 v = __ldg(gI + bw + (size_t)refl(h0 - 5 + m) * PLN);
        const float2 f01 = __half22float2(*reinterpret_cast<const __half2*>(&v.x));
        const float2 f23 = __half22float2(*reinterpret_cast<const __half2*>(&v.y));
        const float2 f4  = __half22float2(*reinterpret_cast<const __half2*>(&v.z));
        win01[m] = pack2(f01.x, f01.y);
        win23[m] = pack2(f23.x, f23.y);
        win4[m]  = f4.x;
    }

    float acc = 0.f;

    #pragma unroll 1
    for (int c = 0; c < (SEG + 11) / 12; ++c) {
        const int jbase = c * 12;
        #pragma unroll
        for (int u = 0; u < 12; ++u) {
            const int j = jbase + u;
            if (j >= SEG) break;
            {   // load plane h0+j+6 into slot (u+11)%12 (read next iter, k=10)
                const uint4 v = __ldg(gI + bw + (size_t)refl(h0 + j + 6) * PLN);
                const float2 f01 = __half22float2(*reinterpret_cast<const __half2*>(&v.x));
                const float2 f23 = __half22float2(*reinterpret_cast<const __half2*>(&v.y));
                const float2 f4  = __half22float2(*reinterpret_cast<const __half2*>(&v.z));
                const int sl = (u + 11) % 12;
                win01[sl] = pack2(f01.x, f01.y);
                win23[sl] = pack2(f23.x, f23.y);
                win4[sl]  = f4.x;
            }
            ull mu12 = 0ULL, mm = 0ULL;
            float m12 = 0.f;
            #pragma unroll
            for (int k = 0; k < 11; ++k) {
                const int sl = (u + k) % 12;
                mu12 = fma2(W2[k], win01[sl], mu12);   // (mu1, mu2)
                mm   = fma2(W2[k], win23[sl], mm);     // (m11, m22)
                m12  = fmaf(GW[k], win4[sl], m12);
            }
            float mu1, mu2, m11, m22;
            unpack2(mu1, mu2, mu12);
            unpack2(m11, m22, mm);

            const float a  = mu1 * mu1;
            const float bb = mu2 * mu2;
            const float cc = mu1 * mu2;
            const float s1 = m11 - a, s2 = m22 - bb, s12 = m12 - cc;
            const float num = (2.f * cc + C1f) * (2.f * s12 + C2f);
            const float den = (a + bb + C1f) * (s1 + s2 + C2f);
            acc += __fdividef(num, den + EPSf);
        }
    }

    // Reduce: 5 warps -> smem -> atomicAdd(double), ticket finalize.
    float v = acc;
    #pragma unroll
    for (int o = 16; o > 0; o >>= 1) v += __shfl_down_sync(0xffffffffu, v, o);
    __shared__ float ws[5];
    if ((threadIdx.x & 31) == 0) ws[threadIdx.x >> 5] = v;
    __syncthreads();
    if (threadIdx.x == 0) {
        const float s = ws[0] + ws[1] + ws[2] + ws[3] + ws[4];
        atomicAdd(&g_acc, (double)s);
        __threadfence();
        const unsigned done = atomicAdd(&g_ticket, 1u);
        if (done == NBBC - 1) {
            const double vv = atomicAdd(&g_acc, 0.0);
            out[0] = (float)(1.0 - vv / (double)NVOX);
            g_acc = 0.0;
            g_ticket = 0u;
            __threadfence();
        }
    }
}

extern "C" void kernel_launch(void* const* d_in, const int* in_sizes, int n_in,
                              void* d_out, int out_size) {
    const float* src = (const float*)d_in[0];
    const float* ref = (const float*)d_in[1];
    float* out = (float*)d_out;

    passDW<<<dim3(HD / WSEG, HD, 2), HD>>>(src, ref);
    passH<<<dim3(HD / SEG, HD, 2), HD>>>(out);
}